// round 10
// baseline (speedup 1.0000x reference)
#include <cuda_runtime.h>
#include <math.h>
#include <math_constants.h>

#define BS 16
#define Q 900
#define NC 92
#define T 100
#define NT (BS * T)   // 1600

#define CQB 12        // q's (=warps) per cost block; Q/CQB = 75
#define LTH 256       // lsa threads
#define LNK 4         // cols per thread in lsa scan
#define NS 4          // q strides per thread in slice-cost (256*4 = 1024)
#define QP 1024       // padded row stride

// Transposed per-batch cost slice, padded: ct[b][t][0..899]=cost, [900..1023]=+INF
__device__ float g_ct[BS][T][QP];

// ---------------------------------------------------------------------------
// Kernel 1: full cost matrix C (unchanged R7 config, 83.8us measured).
// ---------------------------------------------------------------------------
__global__ void __launch_bounds__(32 * CQB) cost_kernel(
    const float* __restrict__ logits,   // [BS*Q, NC]
    const float* __restrict__ pboxes,   // [BS*Q, 4]  cxcywh
    const int*   __restrict__ tgt_ids,  // [NT]
    const float* __restrict__ tbox,     // [NT, 4]    xyxy
    float* __restrict__ C)              // [BS*Q, NT]
{
    const int b     = blockIdx.x / (Q / CQB);
    const int qbase = (blockIdx.x % (Q / CQB)) * CQB;
    const int tid   = threadIdx.x;
    const int lane  = tid & 31;
    const int w     = tid >> 5;
    const int q     = qbase + w;
    const int bq    = b * Q + q;

    __shared__ float4 s_xy[NT];
    __shared__ int    s_id[NT];
    __shared__ float  sp[CQB][NC];

    const float4* tb4 = reinterpret_cast<const float4*>(tbox);
    for (int j = tid; j < NT; j += 32 * CQB) {
        s_xy[j] = __ldg(tb4 + j);
        s_id[j] = __ldg(tgt_ids + j);
    }

    const float* L = logits + (size_t)bq * NC;
    float l0 = (lane      < NC) ? __ldg(L + lane)      : -CUDART_INF_F;
    float l1 = (lane + 32 < NC) ? __ldg(L + lane + 32) : -CUDART_INF_F;
    float l2 = (lane + 64 < NC) ? __ldg(L + lane + 64) : -CUDART_INF_F;

    float m = fmaxf(l0, fmaxf(l1, l2));
    #pragma unroll
    for (int o = 16; o; o >>= 1) m = fmaxf(m, __shfl_xor_sync(0xffffffffu, m, o));

    float e0 = (lane      < NC) ? expf(l0 - m) : 0.f;
    float e1 = (lane + 32 < NC) ? expf(l1 - m) : 0.f;
    float e2 = (lane + 64 < NC) ? expf(l2 - m) : 0.f;
    float s = e0 + e1 + e2;
    #pragma unroll
    for (int o = 16; o; o >>= 1) s += __shfl_xor_sync(0xffffffffu, s, o);
    const float inv_s = 1.0f / s;

    if (lane      < NC) sp[w][lane]      = e0 * inv_s;
    if (lane + 32 < NC) sp[w][lane + 32] = e1 * inv_s;
    if (lane + 64 < NC) sp[w][lane + 64] = e2 * inv_s;
    __syncthreads();

    const float cx = pboxes[bq * 4 + 0];
    const float cy = pboxes[bq * 4 + 1];
    const float wd = pboxes[bq * 4 + 2];
    const float ht = pboxes[bq * 4 + 3];
    const float px0 = cx - wd * 0.5f, py0 = cy - ht * 0.5f;
    const float px1 = cx + wd * 0.5f, py1 = cy + ht * 0.5f;
    const float area_a = (px1 - px0) * (py1 - py0);

    float* Crow = C + (size_t)bq * NT;

    for (int j = lane; j < NT; j += 32) {
        const float prob = sp[w][s_id[j]];

        const float4 tb = s_xy[j];
        const float tx0 = tb.x, ty0 = tb.y, tx1 = tb.z, ty1 = tb.w;

        const float tcx = (tx0 + tx1) * 0.5f, tcy = (ty0 + ty1) * 0.5f;
        const float tw  = tx1 - tx0,          th  = ty1 - ty0;

        const float cb = fabsf(cx - tcx) + fabsf(cy - tcy) + fabsf(wd - tw) + fabsf(ht - th);

        const float area_b = tw * th;
        const float ltx = fmaxf(px0, tx0), lty = fmaxf(py0, ty0);
        const float rbx = fminf(px1, tx1), rby = fminf(py1, ty1);
        const float iw = fmaxf(rbx - ltx, 0.f), ih = fmaxf(rby - lty, 0.f);
        const float inter = iw * ih;
        const float uni = area_a + area_b - inter;
        const float iou = inter / uni;
        const float lcx = fminf(px0, tx0), lcy = fminf(py0, ty0);
        const float rcx = fmaxf(px1, tx1), rcy = fmaxf(py1, ty1);
        const float cw = fmaxf(rcx - lcx, 0.f), ch = fmaxf(rcy - lcy, 0.f);
        const float ac = cw * ch;
        const float giou = iou - (ac - uni) / ac;

        float cost = 5.0f * cb + (-prob);
        cost = cost + 2.0f * (-giou);

        Crow[j] = cost;
    }
}

// ---------------------------------------------------------------------------
// Kernel 2: self-contained LSA. Computes its own batch's 900x100 transposed
// cost slice (independent of kernel 1!), then greedy-init JV assignment.
// Runs CONCURRENTLY with kernel 1 via stream fork.
// ---------------------------------------------------------------------------
__device__ __forceinline__ void amin_combine(float& v, int& i, float v2, int i2) {
    if (v2 < v || (v2 == v && i2 < i)) { v = v2; i = i2; }
}

__global__ void __launch_bounds__(LTH) lsa_kernel(
    const float* __restrict__ logits,
    const float* __restrict__ pboxes,
    const int*   __restrict__ tgt_ids,
    const float* __restrict__ tbox,
    float* __restrict__ rows_out,   // [BS*T]
    float* __restrict__ cols_out)   // [BS*T]
{
    const int b    = blockIdx.x;
    const int tid  = threadIdx.x;
    const int lane = tid & 31;
    const int wid  = tid >> 5;

    __shared__ float4 s_tb[T];
    __shared__ int    s_cid[T];
    __shared__ float u[T + 1];
    __shared__ int   p[QP + 1];
    __shared__ int   sway[QP + 1];
    __shared__ int   ans[T];
    __shared__ int   gcol[T];
    __shared__ int   frees[T];
    __shared__ int   nfree;
    __shared__ unsigned long long red[2][8];

    // ---- Phase A: compute own-batch transposed cost slice ------------------
    if (tid < T) {
        s_tb[tid]  = __ldg(reinterpret_cast<const float4*>(tbox) + b * T + tid);
        s_cid[tid] = __ldg(tgt_ids + b * T + tid);
    }
    for (int k = tid; k <= QP; k += LTH) p[k] = 0;
    __syncthreads();

    const float* Lp[NS];
    float mA[NS], ivA[NS];
    float cxA[NS], cyA[NS], wdA[NS], htA[NS];
    float px0A[NS], py0A[NS], px1A[NS], py1A[NS], arA[NS];

    #pragma unroll
    for (int s = 0; s < NS; ++s) {
        const int q = tid + LTH * s;
        if (q < Q) {
            const float* L = logits + (size_t)(b * Q + q) * NC;
            Lp[s] = L;
            float m = -CUDART_INF_F;
            for (int c = 0; c < NC; ++c) m = fmaxf(m, __ldg(L + c));
            float su = 0.f;
            for (int c = 0; c < NC; ++c) su += __expf(__ldg(L + c) - m);
            mA[s] = m; ivA[s] = 1.0f / su;

            const float4 pb = __ldg(reinterpret_cast<const float4*>(pboxes) + b * Q + q);
            cxA[s] = pb.x; cyA[s] = pb.y; wdA[s] = pb.z; htA[s] = pb.w;
            px0A[s] = pb.x - pb.z * 0.5f;  py0A[s] = pb.y - pb.w * 0.5f;
            px1A[s] = pb.x + pb.z * 0.5f;  py1A[s] = pb.y + pb.w * 0.5f;
            arA[s]  = (px1A[s] - px0A[s]) * (py1A[s] - py0A[s]);
        }
    }

    for (int t = 0; t < T; ++t) {
        const int   id = s_cid[t];
        const float4 tb = s_tb[t];
        const float tx0 = tb.x, ty0 = tb.y, tx1 = tb.z, ty1 = tb.w;
        const float tcx = (tx0 + tx1) * 0.5f, tcy = (ty0 + ty1) * 0.5f;
        const float tw  = tx1 - tx0,          th  = ty1 - ty0;
        const float area_b = tw * th;

        #pragma unroll
        for (int s = 0; s < NS; ++s) {
            const int q = tid + LTH * s;
            float cost = CUDART_INF_F;
            if (q < Q) {
                const float prob = __expf(__ldg(Lp[s] + id) - mA[s]) * ivA[s];

                const float cb = fabsf(cxA[s] - tcx) + fabsf(cyA[s] - tcy)
                               + fabsf(wdA[s] - tw)  + fabsf(htA[s] - th);

                const float ltx = fmaxf(px0A[s], tx0), lty = fmaxf(py0A[s], ty0);
                const float rbx = fminf(px1A[s], tx1), rby = fminf(py1A[s], ty1);
                const float iw = fmaxf(rbx - ltx, 0.f), ih = fmaxf(rby - lty, 0.f);
                const float inter = iw * ih;
                const float uni = arA[s] + area_b - inter;
                const float iou = inter / uni;
                const float lcx = fminf(px0A[s], tx0), lcy = fminf(py0A[s], ty0);
                const float rcx = fmaxf(px1A[s], tx1), rcy = fmaxf(py1A[s], ty1);
                const float cw = fmaxf(rcx - lcx, 0.f), ch = fmaxf(rcy - lcy, 0.f);
                const float ac = cw * ch;
                const float giou = iou - (ac - uni) / ac;

                cost = 5.0f * cb - prob - 2.0f * giou;
            }
            g_ct[b][t][q] = cost;
        }
    }
    __syncthreads();   // block-scope fence: g_ct visible to whole block

    // ---- Phase 0: row mins (one warp per row) ------------------------------
    for (int r = wid; r < T; r += 8) {
        const float* crow = &g_ct[b][r][0];
        float bv = CUDART_INF_F;
        int   bi = 0x7FFFFFF0;
        #pragma unroll
        for (int k = 0; k < QP / 32; ++k) {
            const float c = __ldg(crow + lane + 32 * k);
            if (c < bv) { bv = c; bi = lane + 32 * k; }
        }
        #pragma unroll
        for (int o = 16; o; o >>= 1) {
            const float v2 = __shfl_xor_sync(0xffffffffu, bv, o);
            const int   i2 = __shfl_xor_sync(0xffffffffu, bi, o);
            amin_combine(bv, bi, v2, i2);
        }
        if (lane == 0) { u[r + 1] = bv; gcol[r] = bi + 1; }
    }
    __syncthreads();

    // ---- Phase 0b: greedy assignment ---------------------------------------
    if (tid == 0) {
        int nf = 0;
        for (int i = 1; i <= T; ++i) {
            const int j = gcol[i - 1];
            if (p[j] == 0) p[j] = i;
            else           frees[nf++] = i;
        }
        nfree = nf;
    }
    __syncthreads();

    const int nf = nfree;
    const float* base = &g_ct[b][0][0];
    float    v[LNK];
    unsigned minm[LNK];
    float    val[LNK];
    #pragma unroll
    for (int k = 0; k < LNK; ++k) v[k] = 0.f;
    int itpar = 0;

    // ---- Phase 1: augmenting path per free row -----------------------------
    for (int fi = 0; fi < nf; ++fi) {
        const int i = frees[fi];

        #pragma unroll
        for (int k = 0; k < LNK; ++k) minm[k] = 0xFFFFFFFFu;
        unsigned usedmask = 0;
        if (tid == 0) p[0] = i;

        int   j0   = 0;
        float u_i0 = u[i];
        float D    = 0.f;

        {
            const float* crow = base + (size_t)(i - 1) * QP;
            #pragma unroll
            for (int k = 0; k < LNK; ++k) val[k] = __ldg(crow + tid + LTH * k);
        }

        while (true) {
            {
                const int d = j0 - 1 - tid;
                if (d >= 0 && (d & (LTH - 1)) == 0) usedmask |= 1u << (d >> 8);
            }

            const float adj = u_i0 - D;
            unsigned wmin = 0xFFFFFFFFu;
            unsigned mk[LNK];
            #pragma unroll
            for (int k = 0; k < LNK; ++k) {
                const int jc = 1 + tid + LTH * k;
                const float curf = (val[k] - adj) - v[k];
                const unsigned cu = __float_as_uint(curf);
                const unsigned cm = (cu & 0x80000000u) ? ~cu : (cu | 0x80000000u);
                const bool isused = (usedmask >> k) & 1u;
                if (!isused && cm < minm[k]) { minm[k] = cm; sway[jc] = j0; }
                mk[k] = isused ? 0xFFFFFFFFu : minm[k];
                wmin = umin(wmin, mk[k]);
            }
            const unsigned wbest = __reduce_min_sync(0xffffffffu, wmin);

            unsigned idxc = 0x7FFFFFFFu;
            #pragma unroll
            for (int k = 0; k < LNK; ++k) {
                const int jc = 1 + tid + LTH * k;
                if (mk[k] == wbest) idxc = umin(idxc, (unsigned)jc);
            }
            const unsigned widx = __reduce_min_sync(0xffffffffu, idxc);

            if (lane == 0)
                red[itpar][wid] = ((unsigned long long)wbest << 32) | widx;
            __syncthreads();

            unsigned long long bk = red[itpar][0];
            #pragma unroll
            for (int ww = 1; ww < 8; ++ww) {
                const unsigned long long c2 = red[itpar][ww];
                if (c2 < bk) bk = c2;
            }
            itpar ^= 1;

            const unsigned bm = (unsigned)(bk >> 32);
            const int      j1 = (int)(unsigned)bk;

            const int i0n = p[j1];
            if (i0n) {
                const float* nrow = base + (size_t)(i0n - 1) * QP;
                #pragma unroll
                for (int k = 0; k < LNK; ++k) val[k] = __ldg(nrow + tid + LTH * k);
            }

            const unsigned ub = (bm & 0x80000000u) ? (bm ^ 0x80000000u) : ~bm;
            const float delta_raw = __uint_as_float(ub);
            const float delta = delta_raw - D;
            D = delta_raw;

            unsigned mm = usedmask;
            while (mm) {
                const int k = __ffs(mm) - 1; mm &= mm - 1;
                const int jc = 1 + tid + LTH * k;
                u[p[jc]] += delta;
                v[k] -= delta;
            }
            if (tid == 0) u[i] += delta;

            j0 = j1;
            if (!i0n) break;
            u_i0 = u[i0n];
        }

        __syncthreads();
        if (tid == 0) {
            int j0a = j0;
            while (j0a) {
                const int j1a = sway[j0a];
                p[j0a] = p[j1a];
                j0a = j1a;
            }
        }
        __syncthreads();
    }

    // ---- output ------------------------------------------------------------
    for (int jc = 1 + tid; jc <= Q; jc += LTH) {
        const int r = p[jc];
        if (r > 0) ans[r - 1] = jc - 1;
    }
    __syncthreads();

    if (tid < T) {
        const int a = ans[tid];
        int rank = 0;
        #pragma unroll 4
        for (int tt = 0; tt < T; ++tt) rank += (ans[tt] < a);
        rows_out[b * T + rank] = (float)a;
        cols_out[b * T + rank] = (float)tid;
    }
}

// ---------------------------------------------------------------------------
extern "C" void kernel_launch(void* const* d_in, const int* in_sizes, int n_in,
                              void* d_out, int out_size) {
    const float* logits = (const float*)d_in[0];
    const float* pboxes = (const float*)d_in[1];
    const int*   ids    = (const int*)d_in[2];
    const float* tbox   = (const float*)d_in[3];
    float* out = (float*)d_out;

    const long long CN = (long long)BS * Q * NT;   // 23,040,000

    // lazily-created side stream + events (first call is outside capture)
    static cudaStream_t s_side = nullptr;
    static cudaEvent_t  ev_fork = nullptr, ev_join = nullptr;
    if (!s_side) {
        cudaStreamCreateWithFlags(&s_side, cudaStreamNonBlocking);
        cudaEventCreateWithFlags(&ev_fork, cudaEventDisableTiming);
        cudaEventCreateWithFlags(&ev_join, cudaEventDisableTiming);
    }

    const bool do_lsa = ((long long)out_size >= CN + 2LL * BS * T);

    if (do_lsa) {
        // fork: lsa (self-contained) runs concurrently with the big C kernel
        cudaEventRecord(ev_fork, 0);
        cudaStreamWaitEvent(s_side, ev_fork, 0);
        lsa_kernel<<<BS, LTH, 0, s_side>>>(logits, pboxes, ids, tbox,
                                           out + CN, out + CN + (long long)BS * T);
        cudaEventRecord(ev_join, s_side);
    }

    cost_kernel<<<BS * (Q / CQB), 32 * CQB>>>(logits, pboxes, ids, tbox, out);

    if (do_lsa) {
        cudaStreamWaitEvent(0, ev_join, 0);   // join side chain into main stream
    }
}

// round 11
// speedup vs baseline: 2.5214x; 2.5214x over previous
#include <cuda_runtime.h>
#include <math.h>
#include <math_constants.h>

#define BS 16
#define Q 900
#define NC 92
#define T 100
#define NT (BS * T)   // 1600

#define QB 20         // q per cost block (Q/QB = 45 blocks per batch)
#define NCHK 50       // 1600/32 target chunks
#define CHMAX 7       // max chunks per warp (warps 0,1: 7; others: 6)

#define LTH 256       // lsa threads
#define LNK 4         // cols per thread in lsa scan
#define QP 1024       // padded row stride

// Transposed per-batch cost slice, padded: ct[b][t][0..899]=cost, [900..1023]=+INF
__device__ float g_ct[BS][T][QP];

// ---------------------------------------------------------------------------
// Kernel 1: cost matrix, target-stationary. 8 warps/block; each lane holds
// 6-7 target boxes + ids in REGISTERS; block covers 20 q. Per (q,chunk):
// 2 broadcast LDS + 1 prob LDS + ~30 FP (fast divides) + 1 coalesced STG.
// ---------------------------------------------------------------------------
__global__ void __launch_bounds__(256) cost_kernel(
    const float* __restrict__ logits,   // [BS*Q, NC]
    const float* __restrict__ pboxes,   // [BS*Q, 4]  cxcywh
    const int*   __restrict__ tgt_ids,  // [NT]
    const float* __restrict__ tbox,     // [NT, 4]    xyxy
    float* __restrict__ C)              // [BS*Q, NT]
{
    const int b     = blockIdx.x / (Q / QB);
    const int qbase = (blockIdx.x % (Q / QB)) * QB;
    const int tid   = threadIdx.x;
    const int lane  = tid & 31;
    const int w     = tid >> 5;          // 0..7

    __shared__ float  sp[QB][93];        // softmax probs (padded stride)
    __shared__ float4 spc[QB];           // pred cxcywh
    __shared__ float4 spe[QB];           // pred xyxy
    __shared__ float  sar[QB];           // pred area

    // ---- load this warp's target chunks into registers ----
    float4 txy[CHMAX];
    int    tcid[CHMAX];
    int nch = 0;
    const float4* tb4 = reinterpret_cast<const float4*>(tbox);
    #pragma unroll
    for (int c = w; c < NCHK; c += 8) {
        const int j = c * 32 + lane;
        txy[nch]  = __ldg(tb4 + j);
        tcid[nch] = __ldg(tgt_ids + j);
        ++nch;
    }

    // ---- per-warp softmax for q_local = w, w+8, ... ----
    for (int ql = w; ql < QB; ql += 8) {
        const float* L = logits + (size_t)(b * Q + qbase + ql) * NC;
        float l0 = (lane      < NC) ? __ldg(L + lane)      : -CUDART_INF_F;
        float l1 = (lane + 32 < NC) ? __ldg(L + lane + 32) : -CUDART_INF_F;
        float l2 = (lane + 64 < NC) ? __ldg(L + lane + 64) : -CUDART_INF_F;

        float m = fmaxf(l0, fmaxf(l1, l2));
        #pragma unroll
        for (int o = 16; o; o >>= 1) m = fmaxf(m, __shfl_xor_sync(0xffffffffu, m, o));

        float e0 = (lane      < NC) ? expf(l0 - m) : 0.f;
        float e1 = (lane + 32 < NC) ? expf(l1 - m) : 0.f;
        float e2 = (lane + 64 < NC) ? expf(l2 - m) : 0.f;
        float s = e0 + e1 + e2;
        #pragma unroll
        for (int o = 16; o; o >>= 1) s += __shfl_xor_sync(0xffffffffu, s, o);
        const float inv_s = 1.0f / s;

        if (lane      < NC) sp[ql][lane]      = e0 * inv_s;
        if (lane + 32 < NC) sp[ql][lane + 32] = e1 * inv_s;
        if (lane + 64 < NC) sp[ql][lane + 64] = e2 * inv_s;
    }

    // ---- pred boxes for the block's 20 q ----
    if (tid < QB) {
        const float4 pb = __ldg(reinterpret_cast<const float4*>(pboxes) + b * Q + qbase + tid);
        spc[tid] = pb;
        const float px0 = pb.x - pb.z * 0.5f, py0 = pb.y - pb.w * 0.5f;
        const float px1 = pb.x + pb.z * 0.5f, py1 = pb.y + pb.w * 0.5f;
        spe[tid] = make_float4(px0, py0, px1, py1);
        sar[tid] = (px1 - px0) * (py1 - py0);
    }
    __syncthreads();

    // ---- main: q-major, targets stationary in registers ----
    for (int ql = 0; ql < QB; ++ql) {
        const float4 pc = spc[ql];       // broadcast LDS
        const float4 pe = spe[ql];
        const float  area_a = sar[ql];
        const float* sprow = &sp[ql][0];
        float* Crow = C + (size_t)(b * Q + qbase + ql) * NT;

        #pragma unroll
        for (int k = 0; k < CHMAX; ++k) {
            if (k < nch) {               // warp-uniform
                const float4 tb = txy[k];
                const float prob = sprow[tcid[k]];

                const float tcx = (tb.x + tb.z) * 0.5f, tcy = (tb.y + tb.w) * 0.5f;
                const float tw  = tb.z - tb.x,          th  = tb.w - tb.y;

                const float cb = fabsf(pc.x - tcx) + fabsf(pc.y - tcy)
                               + fabsf(pc.z - tw)  + fabsf(pc.w - th);

                const float area_b = tw * th;
                const float ltx = fmaxf(pe.x, tb.x), lty = fmaxf(pe.y, tb.y);
                const float rbx = fminf(pe.z, tb.z), rby = fminf(pe.w, tb.w);
                const float iw = fmaxf(rbx - ltx, 0.f), ih = fmaxf(rby - lty, 0.f);
                const float inter = iw * ih;
                const float uni = area_a + area_b - inter;
                const float iou = __fdividef(inter, uni);
                const float lcx = fminf(pe.x, tb.x), lcy = fminf(pe.y, tb.y);
                const float rcx = fmaxf(pe.z, tb.z), rcy = fmaxf(pe.w, tb.w);
                const float cw = fmaxf(rcx - lcx, 0.f), ch = fmaxf(rcy - lcy, 0.f);
                const float ac = cw * ch;
                const float giou = iou - __fdividef(ac - uni, ac);

                Crow[(w + 8 * k) * 32 + lane] = 5.0f * cb - prob - 2.0f * giou;
            }
        }
    }
}

// ---------------------------------------------------------------------------
// Kernel 2: smem-tiled transpose C -> g_ct (own-batch slice) + INF padding.
// ---------------------------------------------------------------------------
__global__ void __launch_bounds__(256) transpose_kernel(const float* __restrict__ C)
{
    const int b  = blockIdx.y;
    const int q0 = blockIdx.x * 32;
    const int tx = threadIdx.x;          // 32
    const int ty = threadIdx.y;          // 8

    __shared__ float tile[32][33];

    #pragma unroll
    for (int t0 = 0; t0 < T; t0 += 32) {
        for (int r = ty; r < 32; r += 8) {
            const int q = q0 + r;
            const int t = t0 + tx;
            float v = 0.f;
            if (q < Q && t < T)
                v = __ldg(C + (size_t)(b * Q + q) * NT + b * T + t);
            tile[r][tx] = v;
        }
        __syncthreads();
        for (int r = ty; r < 32; r += 8) {
            const int t = t0 + r;
            if (t < T) {
                const int q = q0 + tx;
                g_ct[b][t][q] = (q < Q) ? tile[tx][r] : CUDART_INF_F;
            }
        }
        __syncthreads();
    }
}

// ---------------------------------------------------------------------------
// Kernel 3: JV LSA with greedy initialization, 256 threads per batch (R9).
// ---------------------------------------------------------------------------
__device__ __forceinline__ void amin_combine(float& v, int& i, float v2, int i2) {
    if (v2 < v || (v2 == v && i2 < i)) { v = v2; i = i2; }
}

__global__ void __launch_bounds__(LTH) lsa_kernel(
    float* __restrict__ rows_out,   // [BS*T]
    float* __restrict__ cols_out)   // [BS*T]
{
    const int b    = blockIdx.x;
    const int tid  = threadIdx.x;
    const int lane = tid & 31;
    const int wid  = tid >> 5;

    __shared__ float u[T + 1];
    __shared__ int   p[QP + 1];
    __shared__ int   sway[QP + 1];
    __shared__ int   ans[T];
    __shared__ int   gcol[T];
    __shared__ int   frees[T];
    __shared__ int   nfree;
    __shared__ unsigned long long red[2][8];

    for (int k = tid; k <= QP; k += LTH) p[k] = 0;

    float    v[LNK];
    unsigned minm[LNK];
    float    val[LNK];
    #pragma unroll
    for (int k = 0; k < LNK; ++k) v[k] = 0.f;

    const float* base = &g_ct[b][0][0];

    // ---- Phase 0: row mins (one warp per row) ----
    for (int r = wid; r < T; r += 8) {
        const float* crow = base + (size_t)r * QP;
        float bv = CUDART_INF_F;
        int   bi = 0x7FFFFFF0;
        #pragma unroll
        for (int k = 0; k < QP / 32; ++k) {
            const float c = __ldg(crow + lane + 32 * k);
            if (c < bv) { bv = c; bi = lane + 32 * k; }
        }
        #pragma unroll
        for (int o = 16; o; o >>= 1) {
            const float v2 = __shfl_xor_sync(0xffffffffu, bv, o);
            const int   i2 = __shfl_xor_sync(0xffffffffu, bi, o);
            amin_combine(bv, bi, v2, i2);
        }
        if (lane == 0) { u[r + 1] = bv; gcol[r] = bi + 1; }
    }
    __syncthreads();

    // ---- Phase 0b: greedy assignment ----
    if (tid == 0) {
        int nf = 0;
        for (int i = 1; i <= T; ++i) {
            const int j = gcol[i - 1];
            if (p[j] == 0) p[j] = i;
            else           frees[nf++] = i;
        }
        nfree = nf;
    }
    __syncthreads();

    const int nf = nfree;
    int itpar = 0;

    // ---- Phase 1: augmenting path per free row ----
    for (int fi = 0; fi < nf; ++fi) {
        const int i = frees[fi];

        #pragma unroll
        for (int k = 0; k < LNK; ++k) minm[k] = 0xFFFFFFFFu;
        unsigned usedmask = 0;
        if (tid == 0) p[0] = i;

        int   j0   = 0;
        float u_i0 = u[i];
        float D    = 0.f;

        {
            const float* crow = base + (size_t)(i - 1) * QP;
            #pragma unroll
            for (int k = 0; k < LNK; ++k) val[k] = __ldg(crow + tid + LTH * k);
        }

        while (true) {
            {
                const int d = j0 - 1 - tid;
                if (d >= 0 && (d & (LTH - 1)) == 0) usedmask |= 1u << (d >> 8);
            }

            const float adj = u_i0 - D;
            unsigned wmin = 0xFFFFFFFFu;
            unsigned mk[LNK];
            #pragma unroll
            for (int k = 0; k < LNK; ++k) {
                const int jc = 1 + tid + LTH * k;
                const float curf = (val[k] - adj) - v[k];
                const unsigned cu = __float_as_uint(curf);
                const unsigned cm = (cu & 0x80000000u) ? ~cu : (cu | 0x80000000u);
                const bool isused = (usedmask >> k) & 1u;
                if (!isused && cm < minm[k]) { minm[k] = cm; sway[jc] = j0; }
                mk[k] = isused ? 0xFFFFFFFFu : minm[k];
                wmin = umin(wmin, mk[k]);
            }
            const unsigned wbest = __reduce_min_sync(0xffffffffu, wmin);

            unsigned idxc = 0x7FFFFFFFu;
            #pragma unroll
            for (int k = 0; k < LNK; ++k) {
                const int jc = 1 + tid + LTH * k;
                if (mk[k] == wbest) idxc = umin(idxc, (unsigned)jc);
            }
            const unsigned widx = __reduce_min_sync(0xffffffffu, idxc);

            if (lane == 0)
                red[itpar][wid] = ((unsigned long long)wbest << 32) | widx;
            __syncthreads();

            unsigned long long bk = red[itpar][0];
            #pragma unroll
            for (int ww = 1; ww < 8; ++ww) {
                const unsigned long long c2 = red[itpar][ww];
                if (c2 < bk) bk = c2;
            }
            itpar ^= 1;

            const unsigned bm = (unsigned)(bk >> 32);
            const int      j1 = (int)(unsigned)bk;

            const int i0n = p[j1];
            if (i0n) {
                const float* nrow = base + (size_t)(i0n - 1) * QP;
                #pragma unroll
                for (int k = 0; k < LNK; ++k) val[k] = __ldg(nrow + tid + LTH * k);
            }

            const unsigned ub = (bm & 0x80000000u) ? (bm ^ 0x80000000u) : ~bm;
            const float delta_raw = __uint_as_float(ub);
            const float delta = delta_raw - D;
            D = delta_raw;

            unsigned mm = usedmask;
            while (mm) {
                const int k = __ffs(mm) - 1; mm &= mm - 1;
                const int jc = 1 + tid + LTH * k;
                u[p[jc]] += delta;
                v[k] -= delta;
            }
            if (tid == 0) u[i] += delta;

            j0 = j1;
            if (!i0n) break;
            u_i0 = u[i0n];
        }

        __syncthreads();
        if (tid == 0) {
            int j0a = j0;
            while (j0a) {
                const int j1a = sway[j0a];
                p[j0a] = p[j1a];
                j0a = j1a;
            }
        }
        __syncthreads();
    }

    // ---- output ----
    for (int jc = 1 + tid; jc <= Q; jc += LTH) {
        const int r = p[jc];
        if (r > 0) ans[r - 1] = jc - 1;
    }
    __syncthreads();

    if (tid < T) {
        const int a = ans[tid];
        int rank = 0;
        #pragma unroll 4
        for (int tt = 0; tt < T; ++tt) rank += (ans[tt] < a);
        rows_out[b * T + rank] = (float)a;
        cols_out[b * T + rank] = (float)tid;
    }
}

// ---------------------------------------------------------------------------
extern "C" void kernel_launch(void* const* d_in, const int* in_sizes, int n_in,
                              void* d_out, int out_size) {
    const float* logits = (const float*)d_in[0];
    const float* pboxes = (const float*)d_in[1];
    const int*   ids    = (const int*)d_in[2];
    const float* tbox   = (const float*)d_in[3];
    float* out = (float*)d_out;

    const long long CN = (long long)BS * Q * NT;   // 23,040,000

    cost_kernel<<<BS * (Q / QB), 256>>>(logits, pboxes, ids, tbox, out);

    dim3 tgrid(32, BS);
    dim3 tblk(32, 8);
    transpose_kernel<<<tgrid, tblk>>>(out);

    if ((long long)out_size >= CN + 2LL * BS * T) {
        lsa_kernel<<<BS, LTH>>>(out + CN, out + CN + (long long)BS * T);
    }
}

// round 12
// speedup vs baseline: 2.7555x; 1.0928x over previous
#include <cuda_runtime.h>
#include <math.h>
#include <math_constants.h>

#define BS 16
#define Q 900
#define NC 92
#define T 100
#define NT (BS * T)   // 1600

#define QB 20         // q per cost block (Q/QB = 45 blocks per batch)
#define NCHK 50       // 1600/32 target chunks
#define CHMAX 7       // max chunks per warp

#define TPB 10        // t per slice block (T/TPB = 10)
#define LTH 256       // lsa threads
#define LNK 4         // cols per thread in lsa scan
#define QP 1024       // padded row stride

// Transposed per-batch cost slice, padded: ct[b][t][0..899]=cost, [900..1023]=+INF
__device__ float g_ct[BS][T][QP];
// per-q softmax stats: x = rowmax, y = 1/sum(exp)
__device__ float2 g_stats[BS * Q];

// ---------------------------------------------------------------------------
// Kernel S1 (side): per-q softmax stats. One warp per q.
// ---------------------------------------------------------------------------
__global__ void __launch_bounds__(256) stats_kernel(const float* __restrict__ logits)
{
    const int qg   = blockIdx.x * 8 + (threadIdx.x >> 5);   // global q index
    const int lane = threadIdx.x & 31;
    if (qg >= BS * Q) return;

    const float* L = logits + (size_t)qg * NC;
    float l0 = (lane      < NC) ? __ldg(L + lane)      : -CUDART_INF_F;
    float l1 = (lane + 32 < NC) ? __ldg(L + lane + 32) : -CUDART_INF_F;
    float l2 = (lane + 64 < NC) ? __ldg(L + lane + 64) : -CUDART_INF_F;

    float m = fmaxf(l0, fmaxf(l1, l2));
    #pragma unroll
    for (int o = 16; o; o >>= 1) m = fmaxf(m, __shfl_xor_sync(0xffffffffu, m, o));

    float s = ((lane      < NC) ? expf(l0 - m) : 0.f)
            + ((lane + 32 < NC) ? expf(l1 - m) : 0.f)
            + ((lane + 64 < NC) ? expf(l2 - m) : 0.f);
    #pragma unroll
    for (int o = 16; o; o >>= 1) s += __shfl_xor_sync(0xffffffffu, s, o);

    if (lane == 0) g_stats[qg] = make_float2(m, 1.0f / s);
}

// ---------------------------------------------------------------------------
// Kernel S2 (side): own-batch transposed cost slice -> g_ct, INF-padded.
// Grid = BS * (T/TPB); block 256; thread q = tid + 256*s.
// ---------------------------------------------------------------------------
__global__ void __launch_bounds__(256) slice_kernel(
    const float* __restrict__ logits,
    const float* __restrict__ pboxes,
    const int*   __restrict__ tgt_ids,
    const float* __restrict__ tbox)
{
    const int b   = blockIdx.x / (T / TPB);
    const int t0  = (blockIdx.x % (T / TPB)) * TPB;
    const int tid = threadIdx.x;

    __shared__ float4 s_tb[TPB];
    __shared__ int    s_id[TPB];
    if (tid < TPB) {
        s_tb[tid] = __ldg(reinterpret_cast<const float4*>(tbox) + b * T + t0 + tid);
        s_id[tid] = __ldg(tgt_ids + b * T + t0 + tid);
    }
    __syncthreads();

    #pragma unroll
    for (int s = 0; s < QP / 256; ++s) {
        const int q = tid + 256 * s;
        if (q < Q) {
            const int bq = b * Q + q;
            const float4 pb = __ldg(reinterpret_cast<const float4*>(pboxes) + bq);
            const float2 st = g_stats[bq];
            const float px0 = pb.x - pb.z * 0.5f, py0 = pb.y - pb.w * 0.5f;
            const float px1 = pb.x + pb.z * 0.5f, py1 = pb.y + pb.w * 0.5f;
            const float area_a = (px1 - px0) * (py1 - py0);
            const float* L = logits + (size_t)bq * NC;

            #pragma unroll
            for (int k = 0; k < TPB; ++k) {
                const float4 tb = s_tb[k];
                const float prob = __expf(__ldg(L + s_id[k]) - st.x) * st.y;

                const float tcx = (tb.x + tb.z) * 0.5f, tcy = (tb.y + tb.w) * 0.5f;
                const float tw  = tb.z - tb.x,          th  = tb.w - tb.y;

                const float cb = fabsf(pb.x - tcx) + fabsf(pb.y - tcy)
                               + fabsf(pb.z - tw)  + fabsf(pb.w - th);

                const float area_b = tw * th;
                const float ltx = fmaxf(px0, tb.x), lty = fmaxf(py0, tb.y);
                const float rbx = fminf(px1, tb.z), rby = fminf(py1, tb.w);
                const float iw = fmaxf(rbx - ltx, 0.f), ih = fmaxf(rby - lty, 0.f);
                const float inter = iw * ih;
                const float uni = area_a + area_b - inter;
                const float iou = __fdividef(inter, uni);
                const float lcx = fminf(px0, tb.x), lcy = fminf(py0, tb.y);
                const float rcx = fmaxf(px1, tb.z), rcy = fmaxf(py1, tb.w);
                const float cw = fmaxf(rcx - lcx, 0.f), ch = fmaxf(rcy - lcy, 0.f);
                const float ac = cw * ch;
                const float giou = iou - __fdividef(ac - uni, ac);

                g_ct[b][t0 + k][q] = 5.0f * cb - prob - 2.0f * giou;
            }
        } else {
            #pragma unroll
            for (int k = 0; k < TPB; ++k) g_ct[b][t0 + k][q] = CUDART_INF_F;
        }
    }
}

// ---------------------------------------------------------------------------
// Kernel M1 (main): full cost matrix C, target-stationary (R11, 44us).
// ---------------------------------------------------------------------------
__global__ void __launch_bounds__(256) cost_kernel(
    const float* __restrict__ logits,
    const float* __restrict__ pboxes,
    const int*   __restrict__ tgt_ids,
    const float* __restrict__ tbox,
    float* __restrict__ C)
{
    const int b     = blockIdx.x / (Q / QB);
    const int qbase = (blockIdx.x % (Q / QB)) * QB;
    const int tid   = threadIdx.x;
    const int lane  = tid & 31;
    const int w     = tid >> 5;

    __shared__ float  sp[QB][93];
    __shared__ float4 spc[QB];
    __shared__ float4 spe[QB];
    __shared__ float  sar[QB];

    float4 txy[CHMAX];
    int    tcid[CHMAX];
    int nch = 0;
    const float4* tb4 = reinterpret_cast<const float4*>(tbox);
    #pragma unroll
    for (int c = w; c < NCHK; c += 8) {
        const int j = c * 32 + lane;
        txy[nch]  = __ldg(tb4 + j);
        tcid[nch] = __ldg(tgt_ids + j);
        ++nch;
    }

    for (int ql = w; ql < QB; ql += 8) {
        const float* L = logits + (size_t)(b * Q + qbase + ql) * NC;
        float l0 = (lane      < NC) ? __ldg(L + lane)      : -CUDART_INF_F;
        float l1 = (lane + 32 < NC) ? __ldg(L + lane + 32) : -CUDART_INF_F;
        float l2 = (lane + 64 < NC) ? __ldg(L + lane + 64) : -CUDART_INF_F;

        float m = fmaxf(l0, fmaxf(l1, l2));
        #pragma unroll
        for (int o = 16; o; o >>= 1) m = fmaxf(m, __shfl_xor_sync(0xffffffffu, m, o));

        float e0 = (lane      < NC) ? expf(l0 - m) : 0.f;
        float e1 = (lane + 32 < NC) ? expf(l1 - m) : 0.f;
        float e2 = (lane + 64 < NC) ? expf(l2 - m) : 0.f;
        float s = e0 + e1 + e2;
        #pragma unroll
        for (int o = 16; o; o >>= 1) s += __shfl_xor_sync(0xffffffffu, s, o);
        const float inv_s = 1.0f / s;

        if (lane      < NC) sp[ql][lane]      = e0 * inv_s;
        if (lane + 32 < NC) sp[ql][lane + 32] = e1 * inv_s;
        if (lane + 64 < NC) sp[ql][lane + 64] = e2 * inv_s;
    }

    if (tid < QB) {
        const float4 pb = __ldg(reinterpret_cast<const float4*>(pboxes) + b * Q + qbase + tid);
        spc[tid] = pb;
        const float px0 = pb.x - pb.z * 0.5f, py0 = pb.y - pb.w * 0.5f;
        const float px1 = pb.x + pb.z * 0.5f, py1 = pb.y + pb.w * 0.5f;
        spe[tid] = make_float4(px0, py0, px1, py1);
        sar[tid] = (px1 - px0) * (py1 - py0);
    }
    __syncthreads();

    for (int ql = 0; ql < QB; ++ql) {
        const float4 pc = spc[ql];
        const float4 pe = spe[ql];
        const float  area_a = sar[ql];
        const float* sprow = &sp[ql][0];
        float* Crow = C + (size_t)(b * Q + qbase + ql) * NT;

        #pragma unroll
        for (int k = 0; k < CHMAX; ++k) {
            if (k < nch) {
                const float4 tb = txy[k];
                const float prob = sprow[tcid[k]];

                const float tcx = (tb.x + tb.z) * 0.5f, tcy = (tb.y + tb.w) * 0.5f;
                const float tw  = tb.z - tb.x,          th  = tb.w - tb.y;

                const float cb = fabsf(pc.x - tcx) + fabsf(pc.y - tcy)
                               + fabsf(pc.z - tw)  + fabsf(pc.w - th);

                const float area_b = tw * th;
                const float ltx = fmaxf(pe.x, tb.x), lty = fmaxf(pe.y, tb.y);
                const float rbx = fminf(pe.z, tb.z), rby = fminf(pe.w, tb.w);
                const float iw = fmaxf(rbx - ltx, 0.f), ih = fmaxf(rby - lty, 0.f);
                const float inter = iw * ih;
                const float uni = area_a + area_b - inter;
                const float iou = __fdividef(inter, uni);
                const float lcx = fminf(pe.x, tb.x), lcy = fminf(pe.y, tb.y);
                const float rcx = fmaxf(pe.z, tb.z), rcy = fmaxf(pe.w, tb.w);
                const float cw = fmaxf(rcx - lcx, 0.f), ch = fmaxf(rcy - lcy, 0.f);
                const float ac = cw * ch;
                const float giou = iou - __fdividef(ac - uni, ac);

                Crow[(w + 8 * k) * 32 + lane] = 5.0f * cb - prob - 2.0f * giou;
            }
        }
    }
}

// ---------------------------------------------------------------------------
// Kernel S3 (side): JV LSA with greedy initialization (R11, unchanged).
// ---------------------------------------------------------------------------
__device__ __forceinline__ void amin_combine(float& v, int& i, float v2, int i2) {
    if (v2 < v || (v2 == v && i2 < i)) { v = v2; i = i2; }
}

__global__ void __launch_bounds__(LTH) lsa_kernel(
    float* __restrict__ rows_out,   // [BS*T]
    float* __restrict__ cols_out)   // [BS*T]
{
    const int b    = blockIdx.x;
    const int tid  = threadIdx.x;
    const int lane = tid & 31;
    const int wid  = tid >> 5;

    __shared__ float u[T + 1];
    __shared__ int   p[QP + 1];
    __shared__ int   sway[QP + 1];
    __shared__ int   ans[T];
    __shared__ int   gcol[T];
    __shared__ int   frees[T];
    __shared__ int   nfree;
    __shared__ unsigned long long red[2][8];

    for (int k = tid; k <= QP; k += LTH) p[k] = 0;

    float    v[LNK];
    unsigned minm[LNK];
    float    val[LNK];
    #pragma unroll
    for (int k = 0; k < LNK; ++k) v[k] = 0.f;

    const float* base = &g_ct[b][0][0];

    // Phase 0: row mins (one warp per row)
    for (int r = wid; r < T; r += 8) {
        const float* crow = base + (size_t)r * QP;
        float bv = CUDART_INF_F;
        int   bi = 0x7FFFFFF0;
        #pragma unroll
        for (int k = 0; k < QP / 32; ++k) {
            const float c = __ldg(crow + lane + 32 * k);
            if (c < bv) { bv = c; bi = lane + 32 * k; }
        }
        #pragma unroll
        for (int o = 16; o; o >>= 1) {
            const float v2 = __shfl_xor_sync(0xffffffffu, bv, o);
            const int   i2 = __shfl_xor_sync(0xffffffffu, bi, o);
            amin_combine(bv, bi, v2, i2);
        }
        if (lane == 0) { u[r + 1] = bv; gcol[r] = bi + 1; }
    }
    __syncthreads();

    // Phase 0b: greedy assignment
    if (tid == 0) {
        int nf = 0;
        for (int i = 1; i <= T; ++i) {
            const int j = gcol[i - 1];
            if (p[j] == 0) p[j] = i;
            else           frees[nf++] = i;
        }
        nfree = nf;
    }
    __syncthreads();

    const int nf = nfree;
    int itpar = 0;

    // Phase 1: augmenting path per free row
    for (int fi = 0; fi < nf; ++fi) {
        const int i = frees[fi];

        #pragma unroll
        for (int k = 0; k < LNK; ++k) minm[k] = 0xFFFFFFFFu;
        unsigned usedmask = 0;
        if (tid == 0) p[0] = i;

        int   j0   = 0;
        float u_i0 = u[i];
        float D    = 0.f;

        {
            const float* crow = base + (size_t)(i - 1) * QP;
            #pragma unroll
            for (int k = 0; k < LNK; ++k) val[k] = __ldg(crow + tid + LTH * k);
        }

        while (true) {
            {
                const int d = j0 - 1 - tid;
                if (d >= 0 && (d & (LTH - 1)) == 0) usedmask |= 1u << (d >> 8);
            }

            const float adj = u_i0 - D;
            unsigned wmin = 0xFFFFFFFFu;
            unsigned mk[LNK];
            #pragma unroll
            for (int k = 0; k < LNK; ++k) {
                const int jc = 1 + tid + LTH * k;
                const float curf = (val[k] - adj) - v[k];
                const unsigned cu = __float_as_uint(curf);
                const unsigned cm = (cu & 0x80000000u) ? ~cu : (cu | 0x80000000u);
                const bool isused = (usedmask >> k) & 1u;
                if (!isused && cm < minm[k]) { minm[k] = cm; sway[jc] = j0; }
                mk[k] = isused ? 0xFFFFFFFFu : minm[k];
                wmin = umin(wmin, mk[k]);
            }
            const unsigned wbest = __reduce_min_sync(0xffffffffu, wmin);

            unsigned idxc = 0x7FFFFFFFu;
            #pragma unroll
            for (int k = 0; k < LNK; ++k) {
                const int jc = 1 + tid + LTH * k;
                if (mk[k] == wbest) idxc = umin(idxc, (unsigned)jc);
            }
            const unsigned widx = __reduce_min_sync(0xffffffffu, idxc);

            if (lane == 0)
                red[itpar][wid] = ((unsigned long long)wbest << 32) | widx;
            __syncthreads();

            unsigned long long bk = red[itpar][0];
            #pragma unroll
            for (int ww = 1; ww < 8; ++ww) {
                const unsigned long long c2 = red[itpar][ww];
                if (c2 < bk) bk = c2;
            }
            itpar ^= 1;

            const unsigned bm = (unsigned)(bk >> 32);
            const int      j1 = (int)(unsigned)bk;

            const int i0n = p[j1];
            if (i0n) {
                const float* nrow = base + (size_t)(i0n - 1) * QP;
                #pragma unroll
                for (int k = 0; k < LNK; ++k) val[k] = __ldg(nrow + tid + LTH * k);
            }

            const unsigned ub = (bm & 0x80000000u) ? (bm ^ 0x80000000u) : ~bm;
            const float delta_raw = __uint_as_float(ub);
            const float delta = delta_raw - D;
            D = delta_raw;

            unsigned mm = usedmask;
            while (mm) {
                const int k = __ffs(mm) - 1; mm &= mm - 1;
                const int jc = 1 + tid + LTH * k;
                u[p[jc]] += delta;
                v[k] -= delta;
            }
            if (tid == 0) u[i] += delta;

            j0 = j1;
            if (!i0n) break;
            u_i0 = u[i0n];
        }

        __syncthreads();
        if (tid == 0) {
            int j0a = j0;
            while (j0a) {
                const int j1a = sway[j0a];
                p[j0a] = p[j1a];
                j0a = j1a;
            }
        }
        __syncthreads();
    }

    // output
    for (int jc = 1 + tid; jc <= Q; jc += LTH) {
        const int r = p[jc];
        if (r > 0) ans[r - 1] = jc - 1;
    }
    __syncthreads();

    if (tid < T) {
        const int a = ans[tid];
        int rank = 0;
        #pragma unroll 4
        for (int tt = 0; tt < T; ++tt) rank += (ans[tt] < a);
        rows_out[b * T + rank] = (float)a;
        cols_out[b * T + rank] = (float)tid;
    }
}

// ---------------------------------------------------------------------------
extern "C" void kernel_launch(void* const* d_in, const int* in_sizes, int n_in,
                              void* d_out, int out_size) {
    const float* logits = (const float*)d_in[0];
    const float* pboxes = (const float*)d_in[1];
    const int*   ids    = (const int*)d_in[2];
    const float* tbox   = (const float*)d_in[3];
    float* out = (float*)d_out;

    const long long CN = (long long)BS * Q * NT;   // 23,040,000

    static cudaStream_t s_side = nullptr;
    static cudaEvent_t  ev_fork = nullptr, ev_join = nullptr;
    if (!s_side) {
        cudaStreamCreateWithFlags(&s_side, cudaStreamNonBlocking);
        cudaEventCreateWithFlags(&ev_fork, cudaEventDisableTiming);
        cudaEventCreateWithFlags(&ev_join, cudaEventDisableTiming);
    }

    const bool do_lsa = ((long long)out_size >= CN + 2LL * BS * T);

    if (do_lsa) {
        // fork: side chain (stats -> slice -> lsa) concurrent with cost_kernel
        cudaEventRecord(ev_fork, 0);
        cudaStreamWaitEvent(s_side, ev_fork, 0);
        stats_kernel<<<(BS * Q + 7) / 8, 256, 0, s_side>>>(logits);
        slice_kernel<<<BS * (T / TPB), 256, 0, s_side>>>(logits, pboxes, ids, tbox);
        lsa_kernel<<<BS, LTH, 0, s_side>>>(out + CN, out + CN + (long long)BS * T);
        cudaEventRecord(ev_join, s_side);
    }

    cost_kernel<<<BS * (Q / QB), 256>>>(logits, pboxes, ids, tbox, out);

    if (do_lsa) {
        cudaStreamWaitEvent(0, ev_join, 0);
    }
}